// round 2
// baseline (speedup 1.0000x reference)
#include <cuda_runtime.h>
#include <math.h>

#define S 16384
#define I 64
#define R 2048
#define H 128
#define O 50
#define NB 128          // persistent scan CTAs (<= SM count, all co-resident)
#define ROWS_PER_CTA 16 // R / NB
#define NT 512          // 16 warps, 1 warp per reservoir row

__device__ float g_states[(size_t)S * R];   // 128 MB scratch: h_t for all t
__device__ float g_wcomb[O * R];            // fused fc2@fc1
__device__ float g_bcomb[O];
__device__ unsigned g_arrive;               // grid barrier counter (reset each call)

// Packed dual-fp32 FMA (Blackwell f32x2 pipe): d.{lo,hi} += a.{lo,hi}*b.{lo,hi}
__device__ __forceinline__ void ffma2(unsigned long long &d,
                                      unsigned long long a,
                                      unsigned long long b) {
    asm("fma.rn.f32x2 %0, %1, %2, %0;" : "+l"(d) : "l"(a), "l"(b));
}
__device__ __forceinline__ float f2lo(unsigned long long v) {
    return __uint_as_float((unsigned)v);
}
__device__ __forceinline__ float f2hi(unsigned long long v) {
    return __uint_as_float((unsigned)(v >> 32));
}

// ---------------------------------------------------------------------------
// Kernel 1: W_comb[o][r] = sum_h fc2_w[o][h]*fc1_w[h][r]; b_comb; reset barrier
// ---------------------------------------------------------------------------
__global__ void wcomb_kernel(const float* __restrict__ fc1_w,
                             const float* __restrict__ fc1_b,
                             const float* __restrict__ fc2_w,
                             const float* __restrict__ fc2_b) {
    const int o = blockIdx.x;
    __shared__ float w2[H];
    if (threadIdx.x < H) w2[threadIdx.x] = fc2_w[o * H + threadIdx.x];
    __syncthreads();
    for (int r = threadIdx.x; r < R; r += blockDim.x) {
        float acc = 0.f;
#pragma unroll 8
        for (int h = 0; h < H; h++) acc += w2[h] * fc1_w[(size_t)h * R + r];
        g_wcomb[o * R + r] = acc;
    }
    if (threadIdx.x == 0) {
        float b = fc2_b[o];
        for (int h = 0; h < H; h++) b += w2[h] * fc1_b[h];
        g_bcomb[o] = b;
        if (o == 0) g_arrive = 0u;   // stream-ordered reset before the scan
    }
}

// ---------------------------------------------------------------------------
// Kernel 2: persistent sequential scan. W resident in registers.
//   warp w of CTA b owns global row rowg = b*16 + w.
//   lane covers W columns {4*lane + 128*k + 0..3}, k = 0..15  (64 cols/lane)
//   and Win columns {2*lane, 2*lane+1}.
// ---------------------------------------------------------------------------
__global__ void __launch_bounds__(NT, 1)
scan_kernel(const float* __restrict__ x,
            const float* __restrict__ Win,
            const float* __restrict__ W) {
    __shared__ float hs[R];   // current h (full vector)
    __shared__ float xs[I];   // current x_t

    const int tid  = threadIdx.x;
    const int warp = tid >> 5;
    const int lane = tid & 31;
    const int rowg = blockIdx.x * ROWS_PER_CTA + warp;

    // --- load this row's W slice into registers (perfectly coalesced) ---
    unsigned long long wA[16], wB[16];
    const float* wrow = W + (size_t)rowg * R;
#pragma unroll
    for (int k = 0; k < 16; k++) {
        ulonglong2 wv = *reinterpret_cast<const ulonglong2*>(wrow + 4 * lane + 128 * k);
        wA[k] = wv.x;
        wB[k] = wv.y;
    }
    const unsigned long long win2 =
        *reinterpret_cast<const unsigned long long*>(Win + (size_t)rowg * I + 2 * lane);

    // --- init h = 0, stage x[0] ---
    *reinterpret_cast<float4*>(&hs[4 * tid]) = make_float4(0.f, 0.f, 0.f, 0.f);
    if (tid < I / 4)
        *reinterpret_cast<float4*>(&xs[4 * tid]) =
            *reinterpret_cast<const float4*>(x + 4 * tid);
    __syncthreads();

    for (int t = 0; t < S; t++) {
        // ---- dot: W[rowg,:] . h  +  Win[rowg,:] . x_t ----
        unsigned long long accA = 0ull, accB = 0ull;
#pragma unroll
        for (int k = 0; k < 16; k++) {
            ulonglong2 h2 = *reinterpret_cast<const ulonglong2*>(&hs[4 * lane + 128 * k]);
            ffma2(accA, wA[k], h2.x);
            ffma2(accB, wB[k], h2.y);
        }
        ffma2(accA, win2, *reinterpret_cast<const unsigned long long*>(&xs[2 * lane]));

        float sum = f2lo(accA) + f2hi(accA) + f2lo(accB) + f2hi(accB);
#pragma unroll
        for (int off = 16; off > 0; off >>= 1)
            sum += __shfl_xor_sync(0xffffffffu, sum, off);

        if (lane == 0) {
            float hn = 0.5f * hs[rowg] + 0.5f * tanhf(sum);   // ALPHA = 0.5
            g_states[(size_t)t * R + rowg] = hn;
        }
        __syncthreads();           // all warps stored & done reading hs
        if (t + 1 == S) break;

        // ---- grid barrier: release-arrive + acquire-spin (monotonic counter) ----
        if (tid == 0) {
            asm volatile("red.release.gpu.add.u32 [%0], %1;"
                         :: "l"(&g_arrive), "r"(1u) : "memory");
            const unsigned target = (unsigned)NB * (unsigned)(t + 1);
            unsigned v;
            do {
                asm volatile("ld.acquire.gpu.u32 %0, [%1];"
                             : "=r"(v) : "l"(&g_arrive) : "memory");
            } while (v < target);
        }
        __syncthreads();

        // ---- reload full h (L2-hot) and stage next x ----
        *reinterpret_cast<float4*>(&hs[4 * tid]) =
            *reinterpret_cast<const float4*>(&g_states[(size_t)t * R + 4 * tid]);
        if (tid < I / 4)
            *reinterpret_cast<float4*>(&xs[4 * tid]) =
                *reinterpret_cast<const float4*>(x + (size_t)(t + 1) * I + 4 * tid);
        __syncthreads();
    }
}

// ---------------------------------------------------------------------------
// Kernel 3: out[t][o] = states[t,:] . W_comb[o,:] + b_comb[o]
//   1 thread per timestep; W_comb chunked through SMEM (broadcast LDS).
// ---------------------------------------------------------------------------
#define KC 128
__global__ void __launch_bounds__(128)
out_kernel(float* __restrict__ out) {
    __shared__ float wcs[O * KC];   // 25.6 KB
    const int t = blockIdx.x * blockDim.x + threadIdx.x;

    float acc[O];
#pragma unroll
    for (int o = 0; o < O; o++) acc[o] = g_bcomb[o];

    for (int kc = 0; kc < R; kc += KC) {
        __syncthreads();
        for (int i = threadIdx.x; i < O * KC; i += blockDim.x) {
            const int o = i / KC, k = i - o * KC;
            wcs[i] = g_wcomb[o * R + kc + k];
        }
        __syncthreads();
        for (int k = 0; k < KC; k += 4) {
            const float4 sv =
                *reinterpret_cast<const float4*>(&g_states[(size_t)t * R + kc + k]);
#pragma unroll
            for (int o = 0; o < O; o++) {
                const float4 wv = *reinterpret_cast<const float4*>(&wcs[o * KC + k]);
                acc[o] += sv.x * wv.x + sv.y * wv.y + sv.z * wv.z + sv.w * wv.w;
            }
        }
    }
#pragma unroll
    for (int o = 0; o < O; o++) out[(size_t)t * O + o] = acc[o];
}

// ---------------------------------------------------------------------------
extern "C" void kernel_launch(void* const* d_in, const int* in_sizes, int n_in,
                              void* d_out, int out_size) {
    const float* x     = (const float*)d_in[0];
    const float* Win   = (const float*)d_in[1];
    const float* W     = (const float*)d_in[2];
    const float* fc1_w = (const float*)d_in[3];
    const float* fc1_b = (const float*)d_in[4];
    const float* fc2_w = (const float*)d_in[5];
    const float* fc2_b = (const float*)d_in[6];
    float* out = (float*)d_out;

    wcomb_kernel<<<O, 256>>>(fc1_w, fc1_b, fc2_w, fc2_b);  // also resets g_arrive
    scan_kernel<<<NB, NT>>>(x, Win, W);
    out_kernel<<<S / 128, 128>>>(out);
}